// round 13
// baseline (speedup 1.0000x reference)
#include <cuda_runtime.h>
#include <math.h>
#include <cstdint>

#define NN 32768
#define NE 524288
#define H 64
#define H2 128
#define NBATCH 16
#define NS 2048
#define NL 4
#define NY 64
#define EPSN 1e-5f
#define GRID_TC 148
#define WPC 8
#define THREADS_TC (WPC * 32)

typedef unsigned long long u64;

__device__ float g_h[NN * H];
__device__ float g_agg[NN * H];
__device__ float g_u[NN * H];
__device__ float g_stats[NBATCH * H * 2];
__device__ float g_X[NN * 3];
__device__ float g_Y[NY * 3];
__device__ double g_acc[3];
// pre-split bf16 features: 32 uint32 (bf16x2 pairs) per node
__device__ uint32_t g_hh[NN * 32];
__device__ uint32_t g_hl[NN * 32];
__device__ uint32_t g_agh[NN * 32];
__device__ uint32_t g_agl[NN * 32];

// ---------- helpers ----------
__device__ __forceinline__ uint32_t smem_u32(const void* p) {
    uint32_t a;
    asm("{ .reg .u64 t; cvta.to.shared.u64 t, %1; cvt.u32.u64 %0, t; }" : "=r"(a) : "l"(p));
    return a;
}
__device__ __forceinline__ uint32_t pack2bf(float f0, float f1) {
    uint32_t r;  // lo half = f0, hi half = f1
    asm("cvt.rn.satfinite.bf16x2.f32 %0, %1, %2;" : "=r"(r) : "f"(f1), "f"(f0));
    return r;
}
__device__ __forceinline__ float bflo(uint32_t h) { return __uint_as_float(h << 16); }
__device__ __forceinline__ float bfhi(uint32_t h) { return __uint_as_float(h & 0xFFFF0000u); }
__device__ __forceinline__ void split2(float f0, float f1, uint32_t& hp, uint32_t& lp) {
    hp = pack2bf(f0, f1);
    lp = pack2bf(f0 - bflo(hp), f1 - bfhi(hp));
}
__device__ __forceinline__ void ldsm4(uint32_t* r, uint32_t addr) {
    asm volatile("ldmatrix.sync.aligned.m8n8.x4.shared.b16 {%0,%1,%2,%3}, [%4];"
        : "=r"(r[0]), "=r"(r[1]), "=r"(r[2]), "=r"(r[3]) : "r"(addr));
}
__device__ __forceinline__ void mma_bf16(float* c, const uint32_t* a, uint32_t b0, uint32_t b1) {
    asm("mma.sync.aligned.m16n8k16.row.col.f32.bf16.bf16.f32 "
        "{%0,%1,%2,%3}, {%4,%5,%6,%7}, {%8,%9}, {%0,%1,%2,%3};"
        : "+f"(c[0]), "+f"(c[1]), "+f"(c[2]), "+f"(c[3])
        : "r"(a[0]), "r"(a[1]), "r"(a[2]), "r"(a[3]), "r"(b0), "r"(b1));
}
__device__ __forceinline__ void cpa16(uint32_t dst, const void* src) {
    asm volatile("cp.async.ca.shared.global [%0], [%1], 16;" :: "r"(dst), "l"(src));
}
__device__ __forceinline__ void cpa_commit() { asm volatile("cp.async.commit_group;"); }
__device__ __forceinline__ void cpa_wait0() { asm volatile("cp.async.wait_group 0;" ::: "memory"); }

// smem byte offsets. Rows padded: W1/A1 272B, W2/A2 144B. Bounce 256B rows.
#define OFF_W1HI 0
#define OFF_W1LO 17408
#define OFF_W2HI 34816
#define OFF_W2LO 44032
#define OFF_B1   53248
#define OFF_B2   53504
#define OFF_A1HI 53760
#define OFF_A1LO 88576
#define OFF_A2HI 123392
#define OFF_A2LO 141824
#define OFF_BNC  160256
#define SMEM_TC  193024

// ======== fused 2-layer MLP on HMMA, cp.async gather of pre-split bf16 ========
// MODE 0: edge MLP, rows = [h[dst]; h[src]], epilogue = float4 atomic scatter.
// MODE 1: node MLP, rows = [h[n]; agg[n]], epilogue = store g_u + IN stats.
template <int MODE>
__global__ void __launch_bounds__(THREADS_TC, 1)
k_mlp_tc(const int* __restrict__ esrc, const int* __restrict__ edst,
         const float* __restrict__ W1, const float* __restrict__ b1,
         const float* __restrict__ W2, const float* __restrict__ b2) {
    extern __shared__ char sm[];
    const uint32_t sb = smem_u32(sm);
    const int tid = threadIdx.x;
    const int wid = tid >> 5, lane = tid & 31;

    // ---- stage weights once per CTA: [n][k] bf16 hi/lo, padded rows ----
    {
        int n = tid >> 2, kq = tid & 3;
#pragma unroll
        for (int p = 0; p < 16; ++p) {
            int k = kq * 32 + 2 * p;
            uint32_t hp, lp;
            split2(W1[k * H + n], W1[(k + 1) * H + n], hp, lp);
            *(uint32_t*)(sm + OFF_W1HI + n * 272 + k * 2) = hp;
            *(uint32_t*)(sm + OFF_W1LO + n * 272 + k * 2) = lp;
        }
#pragma unroll
        for (int p = 0; p < 8; ++p) {
            int k = kq * 16 + 2 * p;
            uint32_t hp, lp;
            split2(W2[k * H + n], W2[(k + 1) * H + n], hp, lp);
            *(uint32_t*)(sm + OFF_W2HI + n * 144 + k * 2) = hp;
            *(uint32_t*)(sm + OFF_W2LO + n * 144 + k * 2) = lp;
        }
        if (tid < H) {
            *(float*)(sm + OFF_B1 + tid * 4) = b1[tid];
            *(float*)(sm + OFF_B2 + tid * 4) = b2[tid];
        }
    }
    __syncthreads();

    const int R = wid * 16;
    const int quad = lane >> 3, r8 = lane & 7;
    const int a_row = R + r8 + (quad & 1) * 8;
    const int a_k8 = (quad >> 1) * 8;
    const int b_nr = r8 + (quad >> 1) * 8;
    const int b_k8 = (quad & 1) * 8;

    const uint32_t a1hiA = sb + OFF_A1HI + a_row * 272 + a_k8 * 2;
    const uint32_t a1loA = sb + OFF_A1LO + a_row * 272 + a_k8 * 2;
    const uint32_t a2hiA = sb + OFF_A2HI + a_row * 144 + a_k8 * 2;
    const uint32_t a2loA = sb + OFF_A2LO + a_row * 144 + a_k8 * 2;
    uint32_t w1hiA[4], w1loA[4], w2hiA[4], w2loA[4];
#pragma unroll
    for (int pi = 0; pi < 4; ++pi) {
        w1hiA[pi] = sb + OFF_W1HI + (pi * 16 + b_nr) * 272 + b_k8 * 2;
        w1loA[pi] = sb + OFF_W1LO + (pi * 16 + b_nr) * 272 + b_k8 * 2;
        w2hiA[pi] = sb + OFF_W2HI + (pi * 16 + b_nr) * 144 + b_k8 * 2;
        w2loA[pi] = sb + OFF_W2LO + (pi * 16 + b_nr) * 144 + b_k8 * 2;
    }

    const float* sB1 = (const float*)(sm + OFF_B1);
    const float* sB2 = (const float*)(sm + OFF_B2);

    const int erow0 = R + (lane >> 2);
    const int ec = (lane & 3) * 2;
    const int srow = lane >> 1, shalf = lane & 1;

    char* e2hi = sm + OFF_A2HI + erow0 * 144;
    char* e2lo = sm + OFF_A2LO + erow0 * 144;
    char* bncW = sm + OFF_BNC + wid * 4096;            // 16 rows x 256B
    char* so0 = bncW + (lane >> 2) * 256;
    const char* sor = bncW + srow * 256;

    // cp.async staging: lane = srow*2+shalf copies one 128B half-row (hi+lo)
    const uint32_t d_hi = sb + OFF_A1HI + (R + srow) * 272 + shalf * 128;
    const uint32_t d_lo = sb + OFF_A1LO + (R + srow) * 272 + shalf * 128;

    const int NGRP = (MODE == 0) ? (NE / 16) : (NN / 16);
    const int STRIDE = GRID_TC * WPC;

    auto stage = [&](int node) {
        const char* shi;
        const char* slo;
        if (MODE == 0) {
            shi = (const char*)g_hh + (size_t)node * 128;
            slo = (const char*)g_hl + (size_t)node * 128;
        } else {
            shi = (const char*)(shalf ? g_agh : g_hh) + (size_t)node * 128;
            slo = (const char*)(shalf ? g_agl : g_hl) + (size_t)node * 128;
        }
#pragma unroll
        for (int j = 0; j < 8; ++j) {
            cpa16(d_hi + j * 16, shi + j * 16);
            cpa16(d_lo + j * 16, slo + j * 16);
        }
        cpa_commit();
    };

    int g = blockIdx.x * WPC + wid;
    int cur_nd = 0, nxt_nd = 0, nxt_node = 0;
    if (g < NGRP) {
        int node;
        if (MODE == 0) {
            int e = g * 16 + srow;
            cur_nd = edst[e];
            node = shalf ? esrc[e] : cur_nd;
        } else {
            node = g * 16 + srow;
        }
        stage(node);
    }

    for (; g < NGRP; g += STRIDE) {
        const int gn = g + STRIDE;
        if (gn < NGRP) {   // prefetch next indices (arrive under GEMM1)
            if (MODE == 0) {
                int e = gn * 16 + srow;
                nxt_nd = edst[e];
                nxt_node = shalf ? esrc[e] : nxt_nd;
            } else {
                nxt_node = gn * 16 + srow;
            }
        }
        cpa_wait0();
        __syncwarp();

        // ---- GEMM1: [16,128] @ W1^T[128,64], 3-pass split ----
        float acc[8][4];
#pragma unroll
        for (int nt = 0; nt < 8; ++nt)
            acc[nt][0] = acc[nt][1] = acc[nt][2] = acc[nt][3] = 0.f;
#pragma unroll
        for (int kt = 0; kt < 8; ++kt) {
            uint32_t ah[4], al[4];
            ldsm4(ah, a1hiA + kt * 32);
            ldsm4(al, a1loA + kt * 32);
#pragma unroll
            for (int pi = 0; pi < 4; ++pi) {
                uint32_t bh[4], bl[4];
                ldsm4(bh, w1hiA[pi] + kt * 32);
                ldsm4(bl, w1loA[pi] + kt * 32);
                mma_bf16(acc[2 * pi], ah, bh[0], bh[1]);
                mma_bf16(acc[2 * pi], ah, bl[0], bl[1]);
                mma_bf16(acc[2 * pi], al, bh[0], bh[1]);
                mma_bf16(acc[2 * pi + 1], ah, bh[2], bh[3]);
                mma_bf16(acc[2 * pi + 1], ah, bl[2], bl[3]);
                mma_bf16(acc[2 * pi + 1], al, bh[2], bh[3]);
            }
        }

        // ---- epi1: bias+relu -> split -> A2 ----
#pragma unroll
        for (int nt = 0; nt < 8; ++nt) {
            int col = nt * 8 + ec;
            float bb0 = sB1[col], bb1 = sB1[col + 1];
            uint32_t hp, lp;
            split2(fmaxf(acc[nt][0] + bb0, 0.f), fmaxf(acc[nt][1] + bb1, 0.f), hp, lp);
            *(uint32_t*)(e2hi + col * 2) = hp;
            *(uint32_t*)(e2lo + col * 2) = lp;
            split2(fmaxf(acc[nt][2] + bb0, 0.f), fmaxf(acc[nt][3] + bb1, 0.f), hp, lp);
            *(uint32_t*)(e2hi + 8 * 144 + col * 2) = hp;
            *(uint32_t*)(e2lo + 8 * 144 + col * 2) = lp;
        }
        __syncwarp();

        // A1 is free now — stage next group (latency hidden under GEMM2+epi2+scatter)
        if (gn < NGRP) stage(nxt_node);

        // ---- GEMM2: [16,64] @ W2^T[64,64] ----
        float acc2[8][4];
#pragma unroll
        for (int nt = 0; nt < 8; ++nt)
            acc2[nt][0] = acc2[nt][1] = acc2[nt][2] = acc2[nt][3] = 0.f;
#pragma unroll
        for (int kt = 0; kt < 4; ++kt) {
            uint32_t ah[4], al[4];
            ldsm4(ah, a2hiA + kt * 32);
            ldsm4(al, a2loA + kt * 32);
#pragma unroll
            for (int pi = 0; pi < 4; ++pi) {
                uint32_t bh[4], bl[4];
                ldsm4(bh, w2hiA[pi] + kt * 32);
                ldsm4(bl, w2loA[pi] + kt * 32);
                mma_bf16(acc2[2 * pi], ah, bh[0], bh[1]);
                mma_bf16(acc2[2 * pi], ah, bl[0], bl[1]);
                mma_bf16(acc2[2 * pi], al, bh[0], bh[1]);
                mma_bf16(acc2[2 * pi + 1], ah, bh[2], bh[3]);
                mma_bf16(acc2[2 * pi + 1], ah, bl[2], bl[3]);
                mma_bf16(acc2[2 * pi + 1], al, bh[2], bh[3]);
            }
        }

        // ---- epi2: bias+relu -> f32 bounce ----
#pragma unroll
        for (int nt = 0; nt < 8; ++nt) {
            int col = nt * 8 + ec;
            float bb0 = sB2[col], bb1 = sB2[col + 1];
            *(float2*)(so0 + col * 4) =
                make_float2(fmaxf(acc2[nt][0] + bb0, 0.f), fmaxf(acc2[nt][1] + bb1, 0.f));
            *(float2*)(so0 + 8 * 256 + col * 4) =
                make_float2(fmaxf(acc2[nt][2] + bb0, 0.f), fmaxf(acc2[nt][3] + bb1, 0.f));
        }
        __syncwarp();

        if (MODE == 0) {
            float* dst = g_agg + (size_t)cur_nd * H + shalf * 32;
#pragma unroll
            for (int i = 0; i < 8; ++i) {
                float4 v = *(const float4*)(sor + (shalf * 32 + i * 4) * 4);
                atomicAdd((float4*)(dst + i * 4), v);
            }
        } else {
            int n = g * 16 + srow;
            float* du = g_u + (size_t)n * H + shalf * 32;
#pragma unroll
            for (int i = 0; i < 8; ++i)
                *(float4*)(du + i * 4) = *(const float4*)(sor + (shalf * 32 + i * 4) * 4);
            float s0 = 0, ss0 = 0, s1 = 0, ss1 = 0;
#pragma unroll
            for (int r = 0; r < 16; ++r) {
                float v0 = *(const float*)(bncW + r * 256 + lane * 4);
                float v1 = *(const float*)(bncW + r * 256 + (lane + 32) * 4);
                s0 += v0; ss0 += v0 * v0;
                s1 += v1; ss1 += v1 * v1;
            }
            int bat = (g * 16) / NS;
            atomicAdd(&g_stats[(bat * H + lane) * 2 + 0], s0);
            atomicAdd(&g_stats[(bat * H + lane) * 2 + 1], ss0);
            atomicAdd(&g_stats[(bat * H + lane + 32) * 2 + 0], s1);
            atomicAdd(&g_stats[(bat * H + lane + 32) * 2 + 1], ss1);
        }
        cur_nd = nxt_nd;
        __syncwarp();
    }
}

// -------------------- encoder: h = x @ enc_W + enc_b, also split hi/lo --------------------
__global__ void k_encode(const float* __restrict__ x, const float* __restrict__ W,
                         const float* __restrict__ b) {
    int idx = blockIdx.x * blockDim.x + threadIdx.x;  // NN*16
    int n = idx >> 4, q = idx & 15;
    float x0 = x[n * 3 + 0], x1 = x[n * 3 + 1], x2 = x[n * 3 + 2];
    float o[4];
#pragma unroll
    for (int j = 0; j < 4; ++j) {
        int c = q * 4 + j;
        o[j] = fmaf(x0, W[c], fmaf(x1, W[H + c], fmaf(x2, W[2 * H + c], b[c])));
    }
    *(float4*)(g_h + n * H + q * 4) = make_float4(o[0], o[1], o[2], o[3]);
    uint32_t h0, l0, h1, l1;
    split2(o[0], o[1], h0, l0);
    split2(o[2], o[3], h1, l1);
    *(uint2*)(g_hh + n * 32 + q * 2) = make_uint2(h0, h1);
    *(uint2*)(g_hl + n * 32 + q * 2) = make_uint2(l0, l1);
}

// -------------------- split agg into bf16 hi/lo --------------------
__global__ void k_aggsplit() {
    int idx = blockIdx.x * blockDim.x + threadIdx.x;  // NN*16
    int n = idx >> 4, q = idx & 15;
    float4 v = *(const float4*)(g_agg + n * H + q * 4);
    uint32_t h0, l0, h1, l1;
    split2(v.x, v.y, h0, l0);
    split2(v.z, v.w, h1, l1);
    *(uint2*)(g_agh + n * 32 + q * 2) = make_uint2(h0, h1);
    *(uint2*)(g_agl + n * 32 + q * 2) = make_uint2(l0, l1);
}

// -------------------- InstanceNorm apply + split hi/lo --------------------
__global__ void k_norm() {
    int idx = blockIdx.x * blockDim.x + threadIdx.x;  // NN*16
    int n = idx >> 4;
    int c = (idx & 15) << 2;
    int b = n >> 11;
    float4 u = *(const float4*)(g_u + n * H + c);
    const float2* st = (const float2*)(g_stats + (b * H + c) * 2);
    float4 r;
    { float2 p = st[0]; float m = p.x * (1.f / NS), v = p.y * (1.f / NS) - m * m; r.x = (u.x - m) * rsqrtf(v + EPSN); }
    { float2 p = st[1]; float m = p.x * (1.f / NS), v = p.y * (1.f / NS) - m * m; r.y = (u.y - m) * rsqrtf(v + EPSN); }
    { float2 p = st[2]; float m = p.x * (1.f / NS), v = p.y * (1.f / NS) - m * m; r.z = (u.z - m) * rsqrtf(v + EPSN); }
    { float2 p = st[3]; float m = p.x * (1.f / NS), v = p.y * (1.f / NS) - m * m; r.w = (u.w - m) * rsqrtf(v + EPSN); }
    *(float4*)(g_h + n * H + c) = r;
    uint32_t h0, l0, h1, l1;
    split2(r.x, r.y, h0, l0);
    split2(r.z, r.w, h1, l1);
    *(uint2*)(g_hh + n * 32 + (c >> 1)) = make_uint2(h0, h1);
    *(uint2*)(g_hl + n * 32 + (c >> 1)) = make_uint2(l0, l1);
}

// -------------------- decoder + normalize --------------------
__global__ void k_decode(const float* __restrict__ W, const float* __restrict__ b,
                         float* __restrict__ out) {
    __shared__ float sW[H * 3];
    __shared__ float sbv[3];
    int tid = threadIdx.x;
    if (tid < H * 3) sW[tid] = W[tid];
    if (tid < 3) sbv[tid] = b[tid];
    __syncthreads();
    int n = blockIdx.x * blockDim.x + tid;
    const float4* hr = (const float4*)(g_h + n * H);
    float a0 = sbv[0], a1 = sbv[1], a2 = sbv[2];
#pragma unroll
    for (int k4 = 0; k4 < 16; k4++) {
        float4 v = hr[k4];
        int k = k4 * 4;
        a0 = fmaf(v.x, sW[(k + 0) * 3 + 0], a0); a1 = fmaf(v.x, sW[(k + 0) * 3 + 1], a1); a2 = fmaf(v.x, sW[(k + 0) * 3 + 2], a2);
        a0 = fmaf(v.y, sW[(k + 1) * 3 + 0], a0); a1 = fmaf(v.y, sW[(k + 1) * 3 + 1], a1); a2 = fmaf(v.y, sW[(k + 1) * 3 + 2], a2);
        a0 = fmaf(v.z, sW[(k + 2) * 3 + 0], a0); a1 = fmaf(v.z, sW[(k + 2) * 3 + 1], a1); a2 = fmaf(v.z, sW[(k + 2) * 3 + 2], a2);
        a0 = fmaf(v.w, sW[(k + 3) * 3 + 0], a0); a1 = fmaf(v.w, sW[(k + 3) * 3 + 1], a1); a2 = fmaf(v.w, sW[(k + 3) * 3 + 2], a2);
    }
    float inv = rsqrtf(a0 * a0 + a1 * a1 + a2 * a2);
    a0 *= inv; a1 *= inv; a2 *= inv;
    g_X[n * 3 + 0] = a0; g_X[n * 3 + 1] = a1; g_X[n * 3 + 2] = a2;
    out[n * 3 + 0] = a0; out[n * 3 + 1] = a1; out[n * 3 + 2] = a2;
}

__global__ void k_fib_kyy() {
    __shared__ float sY[NY * 3];
    __shared__ float wsum[2];
    int i = threadIdx.x;
    double phi = 3.14159265358979323846 * (3.0 - sqrt(5.0));
    double y = 1.0 - 2.0 * (double)i / 63.0;
    double r = sqrt(fmax(0.0, 1.0 - y * y));
    double th = phi * (double)i;
    float Yx = (float)(cos(th) * r), Yy = (float)y, Yz = (float)(sin(th) * r);
    sY[i * 3 + 0] = Yx; sY[i * 3 + 1] = Yy; sY[i * 3 + 2] = Yz;
    g_Y[i * 3 + 0] = Yx; g_Y[i * 3 + 1] = Yy; g_Y[i * 3 + 2] = Yz;
    __syncthreads();
    float acc = 0.f;
    for (int j = 0; j < NY; j++) {
        float d = Yx * sY[j * 3] + Yy * sY[j * 3 + 1] + Yz * sY[j * 3 + 2];
        acc += __expf(fmaf(2.f, d, -2.f));
    }
    for (int o = 16; o > 0; o >>= 1) acc += __shfl_down_sync(0xffffffffu, acc, o);
    if ((i & 31) == 0) wsum[i >> 5] = acc;
    __syncthreads();
    if (i == 0) g_acc[2] = ((double)wsum[0] + (double)wsum[1]) / (64.0 * 64.0);
}

__global__ void k_kxy() {
    __shared__ float sY[NY * 3];
    int tid = threadIdx.x;
    if (tid < NY * 3) sY[tid] = g_Y[tid];
    __syncthreads();
    int n = blockIdx.x * blockDim.x + tid;
    float x0 = g_X[n * 3], x1 = g_X[n * 3 + 1], x2 = g_X[n * 3 + 2];
    float acc = 0.f;
#pragma unroll 4
    for (int j = 0; j < NY; j++) {
        float d = fmaf(x0, sY[j * 3], fmaf(x1, sY[j * 3 + 1], x2 * sY[j * 3 + 2]));
        acc += __expf(fmaf(2.f, d, -2.f));
    }
    for (int o = 16; o > 0; o >>= 1) acc += __shfl_down_sync(0xffffffffu, acc, o);
    if ((tid & 31) == 0) atomicAdd(&g_acc[1], (double)acc);
}

__global__ void __launch_bounds__(128) k_kxx() {
    __shared__ float sx[NS], sy[NS], sz[NS];
    int b = blockIdx.x, tid = threadIdx.x;
    const float* Xb = g_X + b * NS * 3;
    for (int t = tid; t < NS; t += 128) {
        sx[t] = Xb[t * 3]; sy[t] = Xb[t * 3 + 1]; sz[t] = Xb[t * 3 + 2];
    }
    __syncthreads();
    int row = blockIdx.y * 128 + tid;
    float x0 = sx[row], x1 = sy[row], x2 = sz[row];
    float acc = 0.f;
#pragma unroll 4
    for (int j = 0; j < NS; j++) {
        float d = fmaf(x0, sx[j], fmaf(x1, sy[j], x2 * sz[j]));
        acc += __expf(fmaf(2.f, d, -2.f));
    }
    for (int o = 16; o > 0; o >>= 1) acc += __shfl_down_sync(0xffffffffu, acc, o);
    if ((tid & 31) == 0) atomicAdd(&g_acc[0], (double)acc);
}

__global__ void k_final(float* out, int writeLoss) {
    double loss = g_acc[0] / ((double)NBATCH * NS * NS)
                - 2.0 * g_acc[1] / ((double)NBATCH * NS * NY)
                + g_acc[2];
    if (writeLoss) out[0] = (float)loss;
}

extern "C" void kernel_launch(void* const* d_in, const int* in_sizes, int n_in,
                              void* d_out, int out_size) {
    const float* x    = (const float*)d_in[0];
    const int*   esrc = (const int*)d_in[1];
    const int*   edst = (const int*)d_in[2];
    int o = (in_sizes[3] == 1) ? 4 : 3;
    const float* encW = (const float*)d_in[o + 0];
    const float* encb = (const float*)d_in[o + 1];
    const float* m1W  = (const float*)d_in[o + 2];
    const float* m1b  = (const float*)d_in[o + 3];
    const float* m2W  = (const float*)d_in[o + 4];
    const float* m2b  = (const float*)d_in[o + 5];
    const float* u1W  = (const float*)d_in[o + 6];
    const float* u1b  = (const float*)d_in[o + 7];
    const float* u2W  = (const float*)d_in[o + 8];
    const float* u2b  = (const float*)d_in[o + 9];
    const float* decW = (const float*)d_in[o + 10];
    const float* decb = (const float*)d_in[o + 11];
    float* out = (float*)d_out;
    int base = (out_size >= NN * 3 + 1) ? 1 : 0;

    cudaFuncSetAttribute(k_mlp_tc<0>, cudaFuncAttributeMaxDynamicSharedMemorySize, SMEM_TC);
    cudaFuncSetAttribute(k_mlp_tc<1>, cudaFuncAttributeMaxDynamicSharedMemorySize, SMEM_TC);

    void *p_agg, *p_stats, *p_acc;
    cudaGetSymbolAddress(&p_agg, g_agg);
    cudaGetSymbolAddress(&p_stats, g_stats);
    cudaGetSymbolAddress(&p_acc, g_acc);

    k_encode<<<NN * 16 / 256, 256>>>(x, encW, encb);

    for (int l = 0; l < NL; l++) {
        cudaMemsetAsync(p_agg, 0, (size_t)NN * H * sizeof(float));
        k_mlp_tc<0><<<GRID_TC, THREADS_TC, SMEM_TC>>>(esrc, edst,
                                                      m1W + l * H2 * H, m1b + l * H,
                                                      m2W + l * H * H, m2b + l * H);
        k_aggsplit<<<NN * 16 / 256, 256>>>();
        cudaMemsetAsync(p_stats, 0, (size_t)NBATCH * H * 2 * sizeof(float));
        k_mlp_tc<1><<<GRID_TC, THREADS_TC, SMEM_TC>>>(nullptr, nullptr,
                                                      u1W + l * H2 * H, u1b + l * H,
                                                      u2W + l * H * H, u2b + l * H);
        k_norm<<<NN * 16 / 256, 256>>>();
    }

    k_decode<<<NN / 256, 256>>>(decW, decb, out + base);

    cudaMemsetAsync(p_acc, 0, 3 * sizeof(double));
    k_fib_kyy<<<1, 64>>>();
    k_kxy<<<NN / 256, 256>>>();
    dim3 gxx(NBATCH, NS / 128);
    k_kxx<<<gxx, 128>>>();
    k_final<<<1, 1>>>(out, base);
}

// round 17
// speedup vs baseline: 1.2796x; 1.2796x over previous
#include <cuda_runtime.h>
#include <math.h>
#include <cstdint>

#define NN 32768
#define NE 524288
#define H 64
#define H2 128
#define NBATCH 16
#define NS 2048
#define NL 4
#define NY 64
#define EPSN 1e-5f
#define GRID_TC 148
#define WPC 8
#define THREADS_TC (WPC * 32)

typedef unsigned long long u64;

__device__ float g_h[NN * H];
__device__ float g_agg[NN * H];
__device__ float g_u[NN * H];
__device__ float g_stats[NBATCH * H * 2];
__device__ float g_X[NN * 3];
__device__ float g_Y[NY * 3];
__device__ double g_acc[3];
// edge sort scratch
__device__ int g_cnt[NN];
__device__ int g_off[NN];
__device__ int g_sesrc[NE];
__device__ int g_sedst[NE];

// ---------- helpers ----------
__device__ __forceinline__ uint32_t smem_u32(const void* p) {
    uint32_t a;
    asm("{ .reg .u64 t; cvta.to.shared.u64 t, %1; cvt.u32.u64 %0, t; }" : "=r"(a) : "l"(p));
    return a;
}
__device__ __forceinline__ uint32_t pack2bf(float f0, float f1) {
    uint32_t r;  // lo half = f0, hi half = f1
    asm("cvt.rn.satfinite.bf16x2.f32 %0, %1, %2;" : "=r"(r) : "f"(f1), "f"(f0));
    return r;
}
__device__ __forceinline__ float bflo(uint32_t h) { return __uint_as_float(h << 16); }
__device__ __forceinline__ float bfhi(uint32_t h) { return __uint_as_float(h & 0xFFFF0000u); }
__device__ __forceinline__ void split2(float f0, float f1, uint32_t& hp, uint32_t& lp) {
    hp = pack2bf(f0, f1);
    lp = pack2bf(f0 - bflo(hp), f1 - bfhi(hp));
}
__device__ __forceinline__ void ldsm4(uint32_t* r, uint32_t addr) {
    asm volatile("ldmatrix.sync.aligned.m8n8.x4.shared.b16 {%0,%1,%2,%3}, [%4];"
        : "=r"(r[0]), "=r"(r[1]), "=r"(r[2]), "=r"(r[3]) : "r"(addr));
}
__device__ __forceinline__ void mma_bf16(float* c, const uint32_t* a, uint32_t b0, uint32_t b1) {
    asm("mma.sync.aligned.m16n8k16.row.col.f32.bf16.bf16.f32 "
        "{%0,%1,%2,%3}, {%4,%5,%6,%7}, {%8,%9}, {%0,%1,%2,%3};"
        : "+f"(c[0]), "+f"(c[1]), "+f"(c[2]), "+f"(c[3])
        : "r"(a[0]), "r"(a[1]), "r"(a[2]), "r"(a[3]), "r"(b0), "r"(b1));
}

// smem byte offsets. Rows padded: W1/A1 272B (128 bf16 + 8 pad), W2/A2 144B.
#define OFF_W1HI 0
#define OFF_W1LO 17408
#define OFF_W2HI 34816
#define OFF_W2LO 44032
#define OFF_B1   53248
#define OFF_B2   53504
#define OFF_A1HI 53760
#define OFF_A1LO 88576
#define OFF_A2HI 123392
#define OFF_A2LO 141824
#define OFF_DST  160256
#define SMEM_TC  160768

// ======== edge sort: counting sort by dst (edges constant across layers) ========
__global__ void k_hist(const int* __restrict__ edst) {
    int e = blockIdx.x * 256 + threadIdx.x;
    atomicAdd(&g_cnt[edst[e]], 1);
}
__global__ void __launch_bounds__(1024) k_scan() {
    __shared__ int ts[1024];
    int t = threadIdx.x;
    int base = t * 32;
    int loc[32];
    int s = 0;
#pragma unroll
    for (int i = 0; i < 32; ++i) { loc[i] = s; s += g_cnt[base + i]; }
    ts[t] = s;
    __syncthreads();
    for (int off = 1; off < 1024; off <<= 1) {
        int v = (t >= off) ? ts[t - off] : 0;
        __syncthreads();
        ts[t] += v;
        __syncthreads();
    }
    int excl = (t == 0) ? 0 : ts[t - 1];
#pragma unroll
    for (int i = 0; i < 32; ++i) g_off[base + i] = excl + loc[i];
}
__global__ void k_perm(const int* __restrict__ esrc, const int* __restrict__ edst) {
    int e = blockIdx.x * 256 + threadIdx.x;
    int d = edst[e];
    int pos = atomicAdd(&g_off[d], 1);
    g_sesrc[pos] = esrc[e];
    g_sedst[pos] = d;
}

// ======== fused 2-layer MLP on HMMA, 16 rows/warp ========
// MODE 0: edge MLP on dst-sorted edges; epilogue = segmented float2 atomic scatter.
// MODE 1: node MLP, rows = [h[n]; agg[n]]; epilogue = store g_u + IN stats.
template <int MODE>
__global__ void __launch_bounds__(THREADS_TC, 1)
k_mlp_tc(const float* __restrict__ W1, const float* __restrict__ b1,
         const float* __restrict__ W2, const float* __restrict__ b2) {
    extern __shared__ char sm[];
    const uint32_t sb = smem_u32(sm);
    const int tid = threadIdx.x;
    const int wid = tid >> 5, lane = tid & 31;

    // ---- stage weights once per CTA: [n][k] bf16 hi/lo, padded rows ----
    {
        int n = tid >> 2, kq = tid & 3;
#pragma unroll
        for (int p = 0; p < 16; ++p) {
            int k = kq * 32 + 2 * p;
            uint32_t hp, lp;
            split2(W1[k * H + n], W1[(k + 1) * H + n], hp, lp);
            *(uint32_t*)(sm + OFF_W1HI + n * 272 + k * 2) = hp;
            *(uint32_t*)(sm + OFF_W1LO + n * 272 + k * 2) = lp;
        }
#pragma unroll
        for (int p = 0; p < 8; ++p) {
            int k = kq * 16 + 2 * p;
            uint32_t hp, lp;
            split2(W2[k * H + n], W2[(k + 1) * H + n], hp, lp);
            *(uint32_t*)(sm + OFF_W2HI + n * 144 + k * 2) = hp;
            *(uint32_t*)(sm + OFF_W2LO + n * 144 + k * 2) = lp;
        }
        if (tid < H) {
            *(float*)(sm + OFF_B1 + tid * 4) = b1[tid];
            *(float*)(sm + OFF_B2 + tid * 4) = b2[tid];
        }
    }
    __syncthreads();

    const int R = wid * 16;
    const int quad = lane >> 3, r8 = lane & 7;
    const int a_row = R + r8 + (quad & 1) * 8;
    const int a_k8 = (quad >> 1) * 8;
    const int b_nr = r8 + (quad >> 1) * 8;
    const int b_k8 = (quad & 1) * 8;

    const uint32_t a1hiA = sb + OFF_A1HI + a_row * 272 + a_k8 * 2;
    const uint32_t a1loA = sb + OFF_A1LO + a_row * 272 + a_k8 * 2;
    const uint32_t a2hiA = sb + OFF_A2HI + a_row * 144 + a_k8 * 2;
    const uint32_t a2loA = sb + OFF_A2LO + a_row * 144 + a_k8 * 2;
    uint32_t w1hiA[4], w1loA[4], w2hiA[4], w2loA[4];
#pragma unroll
    for (int pi = 0; pi < 4; ++pi) {
        w1hiA[pi] = sb + OFF_W1HI + (pi * 16 + b_nr) * 272 + b_k8 * 2;
        w1loA[pi] = sb + OFF_W1LO + (pi * 16 + b_nr) * 272 + b_k8 * 2;
        w2hiA[pi] = sb + OFF_W2HI + (pi * 16 + b_nr) * 144 + b_k8 * 2;
        w2loA[pi] = sb + OFF_W2LO + (pi * 16 + b_nr) * 144 + b_k8 * 2;
    }

    const float* sB1 = (const float*)(sm + OFF_B1);
    const float* sB2 = (const float*)(sm + OFF_B2);
    int* sDst = (int*)(sm + OFF_DST);

    const int erow0 = R + (lane >> 2);
    const int ec = (lane & 3) * 2;
    const int srow = lane >> 1, shalf = lane & 1;

    char* stHi = sm + OFF_A1HI + (R + srow) * 272 + shalf * 128;
    char* stLo = sm + OFF_A1LO + (R + srow) * 272 + shalf * 128;
    char* e2hi = sm + OFF_A2HI + erow0 * 144;
    char* e2lo = sm + OFF_A2LO + erow0 * 144;
    char* so0 = sm + OFF_A1HI + erow0 * 272;           // f32 out bounce (A1 free post-GEMM1)
    const char* bnc = sm + OFF_A1HI + R * 272;

    const int NGRP = (MODE == 0) ? (NE / 16) : (NN / 16);
    const int STRIDE = GRID_TC * WPC;

    for (int g = blockIdx.x * WPC + wid; g < NGRP; g += STRIDE) {
        // ---- gather + split 16 rows ----
        {
            int node;
            if (MODE == 0) {
                int e = g * 16 + srow;
                int nd = g_sedst[e];
                if (shalf == 0) sDst[R + srow] = nd;
                node = shalf ? g_sesrc[e] : nd;
            } else {
                node = g * 16 + srow;
            }
            const float* base = (MODE == 0) ? g_h : (shalf ? g_agg : g_h);
            const float4* p = (const float4*)(base + (size_t)node * H);
#pragma unroll
            for (int q = 0; q < 8; ++q) {
                float4 v0 = p[2 * q], v1 = p[2 * q + 1];
                uint32_t h0, h1, h2, h3, l0, l1, l2, l3;
                split2(v0.x, v0.y, h0, l0);
                split2(v0.z, v0.w, h1, l1);
                split2(v1.x, v1.y, h2, l2);
                split2(v1.z, v1.w, h3, l3);
                *(uint4*)(stHi + q * 16) = make_uint4(h0, h1, h2, h3);
                *(uint4*)(stLo + q * 16) = make_uint4(l0, l1, l2, l3);
            }
        }
        __syncwarp();

        // ---- GEMM1: [16,128] @ W1^T[128,64], 3-pass split ----
        float acc[8][4];
#pragma unroll
        for (int nt = 0; nt < 8; ++nt)
            acc[nt][0] = acc[nt][1] = acc[nt][2] = acc[nt][3] = 0.f;
#pragma unroll
        for (int kt = 0; kt < 8; ++kt) {
            uint32_t ah[4], al[4];
            ldsm4(ah, a1hiA + kt * 32);
            ldsm4(al, a1loA + kt * 32);
#pragma unroll
            for (int pi = 0; pi < 4; ++pi) {
                uint32_t bh[4], bl[4];
                ldsm4(bh, w1hiA[pi] + kt * 32);
                ldsm4(bl, w1loA[pi] + kt * 32);
                mma_bf16(acc[2 * pi], ah, bh[0], bh[1]);
                mma_bf16(acc[2 * pi], ah, bl[0], bl[1]);
                mma_bf16(acc[2 * pi], al, bh[0], bh[1]);
                mma_bf16(acc[2 * pi + 1], ah, bh[2], bh[3]);
                mma_bf16(acc[2 * pi + 1], ah, bl[2], bl[3]);
                mma_bf16(acc[2 * pi + 1], al, bh[2], bh[3]);
            }
        }

        // ---- epi1: bias+relu -> split -> A2 ----
#pragma unroll
        for (int nt = 0; nt < 8; ++nt) {
            int col = nt * 8 + ec;
            float bb0 = sB1[col], bb1 = sB1[col + 1];
            uint32_t hp, lp;
            split2(fmaxf(acc[nt][0] + bb0, 0.f), fmaxf(acc[nt][1] + bb1, 0.f), hp, lp);
            *(uint32_t*)(e2hi + col * 2) = hp;
            *(uint32_t*)(e2lo + col * 2) = lp;
            split2(fmaxf(acc[nt][2] + bb0, 0.f), fmaxf(acc[nt][3] + bb1, 0.f), hp, lp);
            *(uint32_t*)(e2hi + 8 * 144 + col * 2) = hp;
            *(uint32_t*)(e2lo + 8 * 144 + col * 2) = lp;
        }
        __syncwarp();

        // ---- GEMM2: [16,64] @ W2^T[64,64] ----
        float acc2[8][4];
#pragma unroll
        for (int nt = 0; nt < 8; ++nt)
            acc2[nt][0] = acc2[nt][1] = acc2[nt][2] = acc2[nt][3] = 0.f;
#pragma unroll
        for (int kt = 0; kt < 4; ++kt) {
            uint32_t ah[4], al[4];
            ldsm4(ah, a2hiA + kt * 32);
            ldsm4(al, a2loA + kt * 32);
#pragma unroll
            for (int pi = 0; pi < 4; ++pi) {
                uint32_t bh[4], bl[4];
                ldsm4(bh, w2hiA[pi] + kt * 32);
                ldsm4(bl, w2loA[pi] + kt * 32);
                mma_bf16(acc2[2 * pi], ah, bh[0], bh[1]);
                mma_bf16(acc2[2 * pi], ah, bl[0], bl[1]);
                mma_bf16(acc2[2 * pi], al, bh[0], bh[1]);
                mma_bf16(acc2[2 * pi + 1], ah, bh[2], bh[3]);
                mma_bf16(acc2[2 * pi + 1], ah, bl[2], bl[3]);
                mma_bf16(acc2[2 * pi + 1], al, bh[2], bh[3]);
            }
        }

        // ---- epi2: bias+relu -> f32 bounce ----
#pragma unroll
        for (int nt = 0; nt < 8; ++nt) {
            int col = nt * 8 + ec;
            float bb0 = sB2[col], bb1 = sB2[col + 1];
            *(float2*)(so0 + col * 4) =
                make_float2(fmaxf(acc2[nt][0] + bb0, 0.f), fmaxf(acc2[nt][1] + bb1, 0.f));
            *(float2*)(so0 + 8 * 272 + col * 4) =
                make_float2(fmaxf(acc2[nt][2] + bb0, 0.f), fmaxf(acc2[nt][3] + bb1, 0.f));
        }
        __syncwarp();

        if (MODE == 0) {
            // segmented scatter: lane owns cols (2*lane, 2*lane+1); dst-sorted rows
            int c0 = 2 * lane;
            float ax = 0.f, ay = 0.f;
#pragma unroll
            for (int r = 0; r < 16; ++r) {
                float2 v = *(const float2*)(bnc + r * 272 + c0 * 4);
                ax += v.x; ay += v.y;
                int cur = sDst[R + r];
                int nxt = (r < 15) ? sDst[R + r + 1] : -1;
                if (cur != nxt) {
                    atomicAdd((float2*)(g_agg + (size_t)cur * H + c0), make_float2(ax, ay));
                    ax = 0.f; ay = 0.f;
                }
            }
        } else {
            int n = g * 16 + srow;
            float* du = g_u + (size_t)n * H + shalf * 32;
            const char* sor = sm + OFF_A1HI + (R + srow) * 272;
#pragma unroll
            for (int i = 0; i < 8; ++i)
                *(float4*)(du + i * 4) = *(const float4*)(sor + (shalf * 32 + i * 4) * 4);
            float s0 = 0, ss0 = 0, s1 = 0, ss1 = 0;
#pragma unroll
            for (int r = 0; r < 16; ++r) {
                float v0 = *(const float*)(bnc + r * 272 + lane * 4);
                float v1 = *(const float*)(bnc + r * 272 + (lane + 32) * 4);
                s0 += v0; ss0 += v0 * v0;
                s1 += v1; ss1 += v1 * v1;
            }
            int bat = (g * 16) / NS;
            atomicAdd(&g_stats[(bat * H + lane) * 2 + 0], s0);
            atomicAdd(&g_stats[(bat * H + lane) * 2 + 1], ss0);
            atomicAdd(&g_stats[(bat * H + lane + 32) * 2 + 0], s1);
            atomicAdd(&g_stats[(bat * H + lane + 32) * 2 + 1], ss1);
        }
        __syncwarp();
    }
}

// -------------------- small kernels --------------------
__global__ void k_encode(const float* __restrict__ x, const float* __restrict__ W,
                         const float* __restrict__ b) {
    int idx = blockIdx.x * blockDim.x + threadIdx.x;
    int n = idx >> 6, c = idx & 63;
    float x0 = x[n * 3 + 0], x1 = x[n * 3 + 1], x2 = x[n * 3 + 2];
    g_h[idx] = fmaf(x0, W[c], fmaf(x1, W[H + c], fmaf(x2, W[2 * H + c], b[c])));
}

__global__ void k_norm() {
    int idx = blockIdx.x * blockDim.x + threadIdx.x;
    int n = idx >> 4;
    int c = (idx & 15) << 2;
    int b = n >> 11;
    float4 u = *(const float4*)(g_u + n * H + c);
    const float2* st = (const float2*)(g_stats + (b * H + c) * 2);
    float4 r;
    { float2 p = st[0]; float m = p.x * (1.f / NS), v = p.y * (1.f / NS) - m * m; r.x = (u.x - m) * rsqrtf(v + EPSN); }
    { float2 p = st[1]; float m = p.x * (1.f / NS), v = p.y * (1.f / NS) - m * m; r.y = (u.y - m) * rsqrtf(v + EPSN); }
    { float2 p = st[2]; float m = p.x * (1.f / NS), v = p.y * (1.f / NS) - m * m; r.z = (u.z - m) * rsqrtf(v + EPSN); }
    { float2 p = st[3]; float m = p.x * (1.f / NS), v = p.y * (1.f / NS) - m * m; r.w = (u.w - m) * rsqrtf(v + EPSN); }
    *(float4*)(g_h + n * H + c) = r;
}

__global__ void k_decode(const float* __restrict__ W, const float* __restrict__ b,
                         float* __restrict__ out) {
    __shared__ float sW[H * 3];
    __shared__ float sbv[3];
    int tid = threadIdx.x;
    if (tid < H * 3) sW[tid] = W[tid];
    if (tid < 3) sbv[tid] = b[tid];
    __syncthreads();
    int n = blockIdx.x * blockDim.x + tid;
    const float4* hr = (const float4*)(g_h + n * H);
    float a0 = sbv[0], a1 = sbv[1], a2 = sbv[2];
#pragma unroll
    for (int k4 = 0; k4 < 16; k4++) {
        float4 v = hr[k4];
        int k = k4 * 4;
        a0 = fmaf(v.x, sW[(k + 0) * 3 + 0], a0); a1 = fmaf(v.x, sW[(k + 0) * 3 + 1], a1); a2 = fmaf(v.x, sW[(k + 0) * 3 + 2], a2);
        a0 = fmaf(v.y, sW[(k + 1) * 3 + 0], a0); a1 = fmaf(v.y, sW[(k + 1) * 3 + 1], a1); a2 = fmaf(v.y, sW[(k + 1) * 3 + 2], a2);
        a0 = fmaf(v.z, sW[(k + 2) * 3 + 0], a0); a1 = fmaf(v.z, sW[(k + 2) * 3 + 1], a1); a2 = fmaf(v.z, sW[(k + 2) * 3 + 2], a2);
        a0 = fmaf(v.w, sW[(k + 3) * 3 + 0], a0); a1 = fmaf(v.w, sW[(k + 3) * 3 + 1], a1); a2 = fmaf(v.w, sW[(k + 3) * 3 + 2], a2);
    }
    float inv = rsqrtf(a0 * a0 + a1 * a1 + a2 * a2);
    a0 *= inv; a1 *= inv; a2 *= inv;
    g_X[n * 3 + 0] = a0; g_X[n * 3 + 1] = a1; g_X[n * 3 + 2] = a2;
    out[n * 3 + 0] = a0; out[n * 3 + 1] = a1; out[n * 3 + 2] = a2;
}

__global__ void k_fib_kyy() {
    __shared__ float sY[NY * 3];
    __shared__ float wsum[2];
    int i = threadIdx.x;
    double phi = 3.14159265358979323846 * (3.0 - sqrt(5.0));
    double y = 1.0 - 2.0 * (double)i / 63.0;
    double r = sqrt(fmax(0.0, 1.0 - y * y));
    double th = phi * (double)i;
    float Yx = (float)(cos(th) * r), Yy = (float)y, Yz = (float)(sin(th) * r);
    sY[i * 3 + 0] = Yx; sY[i * 3 + 1] = Yy; sY[i * 3 + 2] = Yz;
    g_Y[i * 3 + 0] = Yx; g_Y[i * 3 + 1] = Yy; g_Y[i * 3 + 2] = Yz;
    __syncthreads();
    float acc = 0.f;
    for (int j = 0; j < NY; j++) {
        float d = Yx * sY[j * 3] + Yy * sY[j * 3 + 1] + Yz * sY[j * 3 + 2];
        acc += __expf(fmaf(2.f, d, -2.f));
    }
    for (int o = 16; o > 0; o >>= 1) acc += __shfl_down_sync(0xffffffffu, acc, o);
    if ((i & 31) == 0) wsum[i >> 5] = acc;
    __syncthreads();
    if (i == 0) g_acc[2] = ((double)wsum[0] + (double)wsum[1]) / (64.0 * 64.0);
}

__global__ void k_kxy() {
    __shared__ float sY[NY * 3];
    int tid = threadIdx.x;
    if (tid < NY * 3) sY[tid] = g_Y[tid];
    __syncthreads();
    int n = blockIdx.x * blockDim.x + tid;
    float x0 = g_X[n * 3], x1 = g_X[n * 3 + 1], x2 = g_X[n * 3 + 2];
    float acc = 0.f;
#pragma unroll 4
    for (int j = 0; j < NY; j++) {
        float d = fmaf(x0, sY[j * 3], fmaf(x1, sY[j * 3 + 1], x2 * sY[j * 3 + 2]));
        acc += __expf(fmaf(2.f, d, -2.f));
    }
    for (int o = 16; o > 0; o >>= 1) acc += __shfl_down_sync(0xffffffffu, acc, o);
    if ((tid & 31) == 0) atomicAdd(&g_acc[1], (double)acc);
}

__global__ void __launch_bounds__(128) k_kxx() {
    __shared__ float sx[NS], sy[NS], sz[NS];
    int b = blockIdx.x, tid = threadIdx.x;
    const float* Xb = g_X + b * NS * 3;
    for (int t = tid; t < NS; t += 128) {
        sx[t] = Xb[t * 3]; sy[t] = Xb[t * 3 + 1]; sz[t] = Xb[t * 3 + 2];
    }
    __syncthreads();
    int row = blockIdx.y * 128 + tid;
    float x0 = sx[row], x1 = sy[row], x2 = sz[row];
    float acc = 0.f;
#pragma unroll 4
    for (int j = 0; j < NS; j++) {
        float d = fmaf(x0, sx[j], fmaf(x1, sy[j], x2 * sz[j]));
        acc += __expf(fmaf(2.f, d, -2.f));
    }
    for (int o = 16; o > 0; o >>= 1) acc += __shfl_down_sync(0xffffffffu, acc, o);
    if ((tid & 31) == 0) atomicAdd(&g_acc[0], (double)acc);
}

__global__ void k_final(float* out, int writeLoss) {
    double loss = g_acc[0] / ((double)NBATCH * NS * NS)
                - 2.0 * g_acc[1] / ((double)NBATCH * NS * NY)
                + g_acc[2];
    if (writeLoss) out[0] = (float)loss;
}

extern "C" void kernel_launch(void* const* d_in, const int* in_sizes, int n_in,
                              void* d_out, int out_size) {
    const float* x    = (const float*)d_in[0];
    const int*   esrc = (const int*)d_in[1];
    const int*   edst = (const int*)d_in[2];
    int o = (in_sizes[3] == 1) ? 4 : 3;
    const float* encW = (const float*)d_in[o + 0];
    const float* encb = (const float*)d_in[o + 1];
    const float* m1W  = (const float*)d_in[o + 2];
    const float* m1b  = (const float*)d_in[o + 3];
    const float* m2W  = (const float*)d_in[o + 4];
    const float* m2b  = (const float*)d_in[o + 5];
    const float* u1W  = (const float*)d_in[o + 6];
    const float* u1b  = (const float*)d_in[o + 7];
    const float* u2W  = (const float*)d_in[o + 8];
    const float* u2b  = (const float*)d_in[o + 9];
    const float* decW = (const float*)d_in[o + 10];
    const float* decb = (const float*)d_in[o + 11];
    float* out = (float*)d_out;
    int base = (out_size >= NN * 3 + 1) ? 1 : 0;

    cudaFuncSetAttribute(k_mlp_tc<0>, cudaFuncAttributeMaxDynamicSharedMemorySize, SMEM_TC);
    cudaFuncSetAttribute(k_mlp_tc<1>, cudaFuncAttributeMaxDynamicSharedMemorySize, SMEM_TC);

    void *p_agg, *p_stats, *p_acc, *p_cnt;
    cudaGetSymbolAddress(&p_agg, g_agg);
    cudaGetSymbolAddress(&p_stats, g_stats);
    cudaGetSymbolAddress(&p_acc, g_acc);
    cudaGetSymbolAddress(&p_cnt, g_cnt);

    // edge sort (once; edges constant across layers)
    cudaMemsetAsync(p_cnt, 0, NN * sizeof(int));
    k_hist<<<NE / 256, 256>>>(edst);
    k_scan<<<1, 1024>>>();
    k_perm<<<NE / 256, 256>>>(esrc, edst);

    k_encode<<<NN * H / 256, 256>>>(x, encW, encb);

    for (int l = 0; l < NL; l++) {
        cudaMemsetAsync(p_agg, 0, (size_t)NN * H * sizeof(float));
        k_mlp_tc<0><<<GRID_TC, THREADS_TC, SMEM_TC>>>(m1W + l * H2 * H, m1b + l * H,
                                                      m2W + l * H * H, m2b + l * H);
        cudaMemsetAsync(p_stats, 0, (size_t)NBATCH * H * 2 * sizeof(float));
        k_mlp_tc<1><<<GRID_TC, THREADS_TC, SMEM_TC>>>(u1W + l * H2 * H, u1b + l * H,
                                                      u2W + l * H * H, u2b + l * H);
        k_norm<<<NN * H / 4 / 256, 256>>>();
    }

    k_decode<<<NN / 256, 256>>>(decW, decb, out + base);

    cudaMemsetAsync(p_acc, 0, 3 * sizeof(double));
    k_fib_kyy<<<1, 64>>>();
    k_kxy<<<NN / 256, 256>>>();
    dim3 gxx(NBATCH, NS / 128);
    k_kxx<<<gxx, 128>>>();
    k_final<<<1, 1>>>(out, base);
}